// round 9
// baseline (speedup 1.0000x reference)
#include <cuda_runtime.h>
#include <math.h>

// NoisyTopKRouter eval-mode:
//   inputs:  x [4,8192,2048] f32, W_gate [2048,8] f32, W_noise (UNUSED), top_k=2
//   outputs (f32, concatenated in d_out):
//     dispatch_weights [N,2], top_k_idx [N,2] (as float), auxiliary_loss scalar
//
// Block-cooperative design: 8 warps/block, warp w owns columns [w*256, w*256+256);
// lane owns 8 fixed columns; weights for those columns live in REGISTERS
// (loaded once per block) -> zero weight traffic in the streaming loop.

#define D        2048
#define D4       512        // D / 4
#define NEXP     8
#define RPB      16         // rows per block
#define WPB      8          // warps per block (256 threads)

__device__ float    g_load[NEXP];
__device__ float    g_imp[NEXP];
__device__ unsigned g_ctr;
// Rearranged W_gate for dense per-warp register loads:
// index (((w*2+grp)*4+j)*2+half)*32 + lane  ->  16B = 2 f32x2 (4 experts)
// for column c = w*256 + grp*128 + lane*4 + j; half0 = experts 0..3, half1 = 4..7.
__device__ float4   g_W2[WPB * 2 * 4 * 2 * 32];   // 64 KB

__device__ __forceinline__ unsigned long long pack2(float x, float y) {
    unsigned long long r;
    asm("mov.b64 %0, {%1, %2};" : "=l"(r) : "f"(x), "f"(y));
    return r;
}
__device__ __forceinline__ void unpack2(unsigned long long v, float& x, float& y) {
    asm("mov.b64 {%0, %1}, %2;" : "=f"(x), "=f"(y) : "l"(v));
}
__device__ __forceinline__ void ffma2(unsigned long long& d,
                                      unsigned long long a, unsigned long long b) {
    asm("fma.rn.f32x2 %0, %1, %2, %0;" : "+l"(d) : "l"(a), "l"(b));
}
__device__ __forceinline__ unsigned long long add2(unsigned long long a,
                                                   unsigned long long b) {
    unsigned long long r;
    asm("add.rn.f32x2 %0, %1, %2;" : "=l"(r) : "l"(a), "l"(b));
    return r;
}

// Rearrange W_gate + zero global accumulators.
__global__ void prep_kernel(const float* __restrict__ Wg) {
    const int c = blockIdx.x * 128 + threadIdx.x;            // column 0..2047
    const float4* Wg4 = (const float4*)Wg;
    const int w = c >> 8, rem = c & 255;
    const int grp = rem >> 7, l = (rem & 127) >> 2, j = rem & 3;
#pragma unroll
    for (int half = 0; half < 2; half++)
        g_W2[((((w * 2 + grp) * 4 + j) * 2) + half) * 32 + l] = Wg4[c * 2 + half];
    if (blockIdx.x == 0) {
        if (threadIdx.x < NEXP) { g_load[threadIdx.x] = 0.f; g_imp[threadIdx.x] = 0.f; }
        if (threadIdx.x == NEXP) g_ctr = 0u;
    }
}

__global__ __launch_bounds__(256, 2)
void router_main(const float* __restrict__ x,
                 float* __restrict__ out_w, float* __restrict__ out_idx,
                 float* __restrict__ out_aux) {
    __shared__ float s_part[WPB * RPB * 9];   // [w][r][e] padded to 9
    __shared__ float s_load[NEXP];
    __shared__ float s_imp[NEXP];
    __shared__ unsigned s_ticket;
    const int tid  = threadIdx.x;
    const int warp = tid >> 5;
    const int lane = tid & 31;

    if (tid < NEXP) { s_load[tid] = 0.f; s_imp[tid] = 0.f; }

    // ---- weights -> registers (once per block; L1-hot dense loads) ----
    const ulonglong2* wq2 = (const ulonglong2*)g_W2;
    unsigned long long w0[16], w1[16];   // w0 = .x (experts pair 0/1 or 4/5), w1 = .y
#pragma unroll
    for (int grp = 0; grp < 2; grp++)
#pragma unroll
        for (int j = 0; j < 4; j++)
#pragma unroll
            for (int half = 0; half < 2; half++) {
                ulonglong2 v = __ldg(&wq2[((((warp * 2 + grp) * 4 + j) * 2) + half) * 32 + lane]);
                w0[grp * 8 + j * 2 + half] = v.x;
                w1[grp * 8 + j * 2 + half] = v.y;
            }

    const int row0 = blockIdx.x * RPB;
    const float4* xp = (const float4*)x + (size_t)row0 * D4 + warp * 64 + lane;

    // Prime depth-2 prefetch.
    float4 xa0 = __ldcs(xp),            xa1 = __ldcs(xp + 32);
    float4 xb0 = __ldcs(xp + D4),       xb1 = __ldcs(xp + D4 + 32);

#pragma unroll 1
    for (int r = 0; r < RPB; r++) {
        float4 xc0, xc1;
        if (r + 2 < RPB) {
            xc0 = __ldcs(xp + (r + 2) * D4);
            xc1 = __ldcs(xp + (r + 2) * D4 + 32);
        }

        unsigned long long h[4] = {0ull, 0ull, 0ull, 0ull};
#pragma unroll
        for (int grp = 0; grp < 2; grp++) {
            const float4 xv = grp ? xa1 : xa0;
#pragma unroll
            for (int j = 0; j < 4; j++) {
                float xc = (j == 0) ? xv.x : (j == 1) ? xv.y : (j == 2) ? xv.z : xv.w;
                unsigned long long xb = pack2(xc, xc);
                const int b = grp * 8 + j * 2;
                ffma2(h[0], xb, w0[b]);       // experts 0,1
                ffma2(h[1], xb, w1[b]);       // experts 2,3
                ffma2(h[2], xb, w0[b + 1]);   // experts 4,5
                ffma2(h[3], xb, w1[b + 1]);   // experts 6,7
            }
        }

        // Butterfly: full 32-lane sum of the warp's 256-column partial.
#pragma unroll
        for (int p = 0; p < 4; p++)
#pragma unroll
            for (int off = 16; off > 0; off >>= 1)
                h[p] = add2(h[p], __shfl_xor_sync(0xffffffffu, h[p], off));

        // Lanes 0..7 stash expert e = lane for this (warp, row).
        if (lane < NEXP) {
            float lo, hi;
            unpack2(h[lane >> 1], lo, hi);
            s_part[(warp * RPB + r) * 9 + lane] = (lane & 1) ? hi : lo;
        }

        xa0 = xb0; xa1 = xb1; xb0 = xc0; xb1 = xc1;
    }

    __syncthreads();

    // ---- epilogue: one thread per row ----
    if (tid < RPB) {
        const int r = tid, row = row0 + r;
        float h[NEXP];
#pragma unroll
        for (int e = 0; e < NEXP; e++) {
            float s = 0.f;
#pragma unroll
            for (int w = 0; w < WPB; w++) s += s_part[(w * RPB + r) * 9 + e];
            h[e] = s;
        }

        // top-2 (lowest index wins ties, matching jax.lax.top_k)
        int e0 = 0; float v0 = h[0];
#pragma unroll
        for (int e = 1; e < NEXP; e++)
            if (h[e] > v0) { v0 = h[e]; e0 = e; }
        int e1 = -1; float v1 = -3.4e38f;
#pragma unroll
        for (int e = 0; e < NEXP; e++)
            if (e != e0 && h[e] > v1) { v1 = h[e]; e1 = e; }

        float wgt0 = 1.f / (1.f + expf(v1 - v0));
        float wgt1 = 1.f - wgt0;

        float p[NEXP]; float Z = 0.f;
#pragma unroll
        for (int e = 0; e < NEXP; e++) { p[e] = expf(h[e] - v0); Z += p[e]; }
        float invZ = 1.f / Z;
#pragma unroll
        for (int e = 0; e < NEXP; e++) atomicAdd(&s_imp[e], p[e] * invZ);
        atomicAdd(&s_load[e0], 1.f);
        atomicAdd(&s_load[e1], 1.f);

        out_w[row * 2]       = wgt0;
        out_w[row * 2 + 1]   = wgt1;
        out_idx[row * 2]     = (float)e0;
        out_idx[row * 2 + 1] = (float)e1;
    }

    __syncthreads();
    if (tid < NEXP) {
        atomicAdd(&g_load[tid], s_load[tid]);
        atomicAdd(&g_imp[tid],  s_imp[tid]);
        __threadfence();
    }
    __syncthreads();
    if (tid == 0) s_ticket = atomicAdd(&g_ctr, 1u);
    __syncthreads();

    // Last block computes the auxiliary loss.
    if (s_ticket == gridDim.x - 1 && tid == 0) {
        volatile float* vl_ = g_load;
        volatile float* vi_ = g_imp;
        float l[NEXP], im[NEXP];
        float ml = 0.f, mi = 0.f;
#pragma unroll
        for (int e = 0; e < NEXP; e++) {
            l[e] = vl_[e]; im[e] = vi_[e];
            ml += l[e];    mi += im[e];
        }
        ml *= (1.f / NEXP);
        mi *= (1.f / NEXP);
        float vl = 0.f, vi = 0.f;
#pragma unroll
        for (int e = 0; e < NEXP; e++) {
            float dl = l[e]  - ml; vl += dl * dl;
            float di = im[e] - mi; vi += di * di;
        }
        vl *= (1.f / (NEXP - 1));   // ddof = 1
        vi *= (1.f / (NEXP - 1));
        float cv = sqrtf(vl) / (ml + 1e-6f) + sqrtf(vi) / (mi + 1e-6f);
        *out_aux = cv * 0.01f;
    }
}

extern "C" void kernel_launch(void* const* d_in, const int* in_sizes, int n_in,
                              void* d_out, int out_size) {
    const float* x  = (const float*)d_in[0];   // [4,8192,2048]
    const float* Wg = (const float*)d_in[1];   // [2048,8]
    // d_in[2] = W_noise (unused in eval), d_in[3] = top_k (=2)

    const int N = in_sizes[0] / D;             // 32768 rows

    float* out     = (float*)d_out;
    float* out_w   = out;                      // [N,2]
    float* out_idx = out + (size_t)N * 2;      // [N,2]
    float* out_aux = out + (size_t)N * 4;      // scalar

    prep_kernel<<<16, 128>>>(Wg);
    router_main<<<N / RPB, 256>>>(x, out_w, out_idx, out_aux);
}

// round 10
// speedup vs baseline: 1.4143x; 1.4143x over previous
#include <cuda_runtime.h>
#include <math.h>

// NoisyTopKRouter eval-mode:
//   inputs:  x [4,8192,2048] f32, W_gate [2048,8] f32, W_noise (UNUSED), top_k=2
//   outputs (f32, concatenated in d_out):
//     dispatch_weights [N,2], top_k_idx [N,2] (as float), auxiliary_loss scalar
//
// Bulk-copy design: each 64-thread block owns 4 contiguous rows (32 KB, one
// cp.async.bulk global->smem). Warp w processes the column-half w of all 4 rows
// (weights amortized over 4 rows, L1-hot). The TMA/bulk engine owns DRAM
// latency hiding; no per-lane LSU x-loads at all.

#define D        2048
#define D4       512        // D / 4
#define NEXP     8
#define RPB      4          // rows per block (32 KB contiguous)
#define XBYTES   (RPB * D * 4)

__device__ float    g_load[NEXP];
__device__ float    g_imp[NEXP];
__device__ unsigned g_ctr;
// Rearranged W_gate: [(cb*4+j)*2 + half][lane] 16B units; half0 = experts 0..3,
// half1 = experts 4..7, for column c = cb*128 + lane*4 + j  (cb = 0..15).
__device__ float4   g_Wre[16 * 4 * 2 * 32];   // 64 KB

__device__ __forceinline__ unsigned long long pack2(float x, float y) {
    unsigned long long r;
    asm("mov.b64 %0, {%1, %2};" : "=l"(r) : "f"(x), "f"(y));
    return r;
}
__device__ __forceinline__ void unpack2(unsigned long long v, float& x, float& y) {
    asm("mov.b64 {%0, %1}, %2;" : "=f"(x), "=f"(y) : "l"(v));
}
__device__ __forceinline__ void ffma2(unsigned long long& d,
                                      unsigned long long a, unsigned long long b) {
    asm("fma.rn.f32x2 %0, %1, %2, %0;" : "+l"(d) : "l"(a), "l"(b));
}
__device__ __forceinline__ unsigned long long add2(unsigned long long a,
                                                   unsigned long long b) {
    unsigned long long r;
    asm("add.rn.f32x2 %0, %1, %2;" : "=l"(r) : "l"(a), "l"(b));
    return r;
}
__device__ __forceinline__ void bulk_g2s(void* sdst, const void* gsrc,
                                         unsigned bytes, unsigned mbar) {
    unsigned d = (unsigned)__cvta_generic_to_shared(sdst);
    asm volatile(
        "cp.async.bulk.shared::cta.global.mbarrier::complete_tx::bytes [%0], [%1], %2, [%3];"
        :: "r"(d), "l"(gsrc), "r"(bytes), "r"(mbar) : "memory");
}

// Rearrange W_gate + zero global accumulators.
__global__ void prep_kernel(const float* __restrict__ Wg) {
    const int c = blockIdx.x * 128 + threadIdx.x;            // column 0..2047
    const float4* Wg4 = (const float4*)Wg;
    float4 f0 = Wg4[c * 2];                                   // experts 0..3
    float4 f1 = Wg4[c * 2 + 1];                               // experts 4..7
    const int i = c >> 7, r = c & 127, lane = r >> 2, j = r & 3;
    const int base = ((i * 4 + j) * 2) * 32 + lane;
    g_Wre[base]      = f0;
    g_Wre[base + 32] = f1;
    if (blockIdx.x == 0) {
        if (threadIdx.x < NEXP) { g_load[threadIdx.x] = 0.f; g_imp[threadIdx.x] = 0.f; }
        if (threadIdx.x == NEXP) g_ctr = 0u;
    }
}

__global__ __launch_bounds__(64)
void router_main(const float* __restrict__ x,
                 float* __restrict__ out_w, float* __restrict__ out_idx,
                 float* __restrict__ out_aux) {
    __shared__ __align__(16) float4 s_x[RPB * D4];   // 32 KB
    __shared__ float s_part[2][RPB][NEXP];
    __shared__ float s_load[NEXP];
    __shared__ float s_imp[NEXP];
    __shared__ __align__(8) unsigned long long s_mbar;
    __shared__ unsigned s_ticket;

    const int tid  = threadIdx.x;
    const int h    = tid >> 5;        // warp = column half
    const int lane = tid & 31;
    const unsigned mbar = (unsigned)__cvta_generic_to_shared(&s_mbar);

    if (tid < NEXP) { s_load[tid] = 0.f; s_imp[tid] = 0.f; }
    if (tid == 0) {
        asm volatile("mbarrier.init.shared.b64 [%0], %1;" :: "r"(mbar), "r"(1));
        asm volatile("fence.proxy.async.shared::cta;" ::: "memory");
    }
    __syncthreads();

    const int row0 = blockIdx.x * RPB;
    if (tid == 0) {
        asm volatile("mbarrier.arrive.expect_tx.shared.b64 _, [%0], %1;"
                     :: "r"(mbar), "r"((unsigned)XBYTES));
        bulk_g2s(s_x, x + (size_t)row0 * D, XBYTES, mbar);
    }

    // Warm the weight L1 while the bulk copy is in flight.
    const ulonglong2* wq = (const ulonglong2*)g_Wre;
    unsigned long long acc[RPB][4];
#pragma unroll
    for (int rr = 0; rr < RPB; rr++)
#pragma unroll
        for (int p = 0; p < 4; p++) acc[rr][p] = 0ull;

    // Wait for the tile (acquire orders subsequent LDS after TMA writes).
    {
        unsigned done;
        do {
            asm volatile(
                "{\n\t.reg .pred p;\n\t"
                "mbarrier.try_wait.parity.acquire.cta.shared::cta.b64 p, [%1], %2, 0x989680;\n\t"
                "selp.b32 %0, 1, 0, p;\n\t}"
                : "=r"(done) : "r"(mbar), "r"(0u) : "memory");
        } while (!done);
    }

    // ---- main compute: warp h covers columns [h*1024, h*1024+1024) of 4 rows ----
    const int sbase = h * 256 + lane;        // float4 index within a row slice

    float4 xv[RPB];
#pragma unroll
    for (int rr = 0; rr < RPB; rr++)
        xv[rr] = s_x[rr * D4 + sbase];       // ii = 0

#pragma unroll
    for (int ii = 0; ii < 8; ii++) {
        float4 xn[RPB];
        if (ii < 7) {
#pragma unroll
            for (int rr = 0; rr < RPB; rr++)
                xn[rr] = s_x[rr * D4 + sbase + (ii + 1) * 32];
        }

        const int cb = h * 8 + ii;           // column block 0..15
#pragma unroll
        for (int j = 0; j < 4; j++) {
            ulonglong2 wa = wq[((cb * 4 + j) * 2 + 0) * 32 + lane];  // experts 0..3
            ulonglong2 wb = wq[((cb * 4 + j) * 2 + 1) * 32 + lane];  // experts 4..7
#pragma unroll
            for (int rr = 0; rr < RPB; rr++) {
                float xc = (j == 0) ? xv[rr].x : (j == 1) ? xv[rr].y
                         : (j == 2) ? xv[rr].z : xv[rr].w;
                unsigned long long xb = pack2(xc, xc);
                ffma2(acc[rr][0], xb, wa.x);
                ffma2(acc[rr][1], xb, wa.y);
                ffma2(acc[rr][2], xb, wb.x);
                ffma2(acc[rr][3], xb, wb.y);
            }
        }

#pragma unroll
        for (int rr = 0; rr < RPB; rr++) xv[rr] = xn[rr];
    }

    // Cross-lane reduction ONCE at the end (16 independent 5-step chains).
#pragma unroll
    for (int rr = 0; rr < RPB; rr++)
#pragma unroll
        for (int p = 0; p < 4; p++) {
#pragma unroll
            for (int off = 16; off > 0; off >>= 1)
                acc[rr][p] = add2(acc[rr][p],
                                  __shfl_xor_sync(0xffffffffu, acc[rr][p], off));
        }

    // Lanes 0..7 stash expert e = lane for each row (this warp's col-half).
    if (lane < NEXP) {
#pragma unroll
        for (int rr = 0; rr < RPB; rr++) {
            float lo, hi;
            unpack2(acc[rr][lane >> 1], lo, hi);
            s_part[h][rr][lane] = (lane & 1) ? hi : lo;
        }
    }
    __syncthreads();

    // ---- epilogue: one thread per row ----
    if (tid < RPB) {
        const int r = tid, row = row0 + r;
        float hh[NEXP];
#pragma unroll
        for (int e = 0; e < NEXP; e++)
            hh[e] = s_part[0][r][e] + s_part[1][r][e];

        // top-2 (lowest index wins ties, matching jax.lax.top_k)
        int e0 = 0; float v0 = hh[0];
#pragma unroll
        for (int e = 1; e < NEXP; e++)
            if (hh[e] > v0) { v0 = hh[e]; e0 = e; }
        int e1 = -1; float v1 = -3.4e38f;
#pragma unroll
        for (int e = 0; e < NEXP; e++)
            if (e != e0 && hh[e] > v1) { v1 = hh[e]; e1 = e; }

        float w0 = 1.f / (1.f + expf(v1 - v0));
        float w1 = 1.f - w0;

        float p[NEXP]; float Z = 0.f;
#pragma unroll
        for (int e = 0; e < NEXP; e++) { p[e] = expf(hh[e] - v0); Z += p[e]; }
        float invZ = 1.f / Z;
#pragma unroll
        for (int e = 0; e < NEXP; e++) atomicAdd(&s_imp[e], p[e] * invZ);
        atomicAdd(&s_load[e0], 1.f);
        atomicAdd(&s_load[e1], 1.f);

        out_w[row * 2]       = w0;
        out_w[row * 2 + 1]   = w1;
        out_idx[row * 2]     = (float)e0;
        out_idx[row * 2 + 1] = (float)e1;
    }

    __syncthreads();
    if (tid < NEXP) {
        atomicAdd(&g_load[tid], s_load[tid]);
        atomicAdd(&g_imp[tid],  s_imp[tid]);
        __threadfence();
    }
    __syncthreads();
    if (tid == 0) s_ticket = atomicAdd(&g_ctr, 1u);
    __syncthreads();

    // Last block computes the auxiliary loss.
    if (s_ticket == gridDim.x - 1 && tid == 0) {
        volatile float* vl_ = g_load;
        volatile float* vi_ = g_imp;
        float l[NEXP], im[NEXP];
        float ml = 0.f, mi = 0.f;
#pragma unroll
        for (int e = 0; e < NEXP; e++) {
            l[e] = vl_[e]; im[e] = vi_[e];
            ml += l[e];    mi += im[e];
        }
        ml *= (1.f / NEXP);
        mi *= (1.f / NEXP);
        float vl = 0.f, vi = 0.f;
#pragma unroll
        for (int e = 0; e < NEXP; e++) {
            float dl = l[e]  - ml; vl += dl * dl;
            float di = im[e] - mi; vi += di * di;
        }
        vl *= (1.f / (NEXP - 1));   // ddof = 1
        vi *= (1.f / (NEXP - 1));
        float cv = sqrtf(vl) / (ml + 1e-6f) + sqrtf(vi) / (mi + 1e-6f);
        *out_aux = cv * 0.01f;
    }
}

extern "C" void kernel_launch(void* const* d_in, const int* in_sizes, int n_in,
                              void* d_out, int out_size) {
    const float* x  = (const float*)d_in[0];   // [4,8192,2048]
    const float* Wg = (const float*)d_in[1];   // [2048,8]
    // d_in[2] = W_noise (unused in eval), d_in[3] = top_k (=2)

    const int N = in_sizes[0] / D;             // 32768 rows

    float* out     = (float*)d_out;
    float* out_w   = out;                      // [N,2]
    float* out_idx = out + (size_t)N * 2;      // [N,2]
    float* out_aux = out + (size_t)N * 4;      // scalar

    prep_kernel<<<16, 128>>>(Wg);
    router_main<<<N / RPB, 64>>>(x, out_w, out_idx, out_aux);
}